// round 1
// baseline (speedup 1.0000x reference)
#include <cuda_runtime.h>
#include <math.h>

#define NODE  400
#define TRS   40
#define STEPS 10
#define OUTN  64
#define DMAXC 500
#define BUF   512
#define DTF   0.1f

// ---- persistent scratch (device globals; no allocation) ----
__device__ float  g_rowSS[3 * NODE];
__device__ float  g_invnorm[3];       // [b, f, l]
__device__ float  g_rs[NODE * 3];     // raw row sums [b,f,l] per node
__device__ float4 g_K4[NODE * BUF];   // per-node delay histogram (x=b,y=f,z=l)
__device__ int    g_dmax;
__device__ float  g_colmean[NODE];
__device__ float  g_Vsnap[TRS * NODE];

__device__ __forceinline__ float reluf(float x) { return x > 0.f ? x : 0.f; }

// ---------------------------------------------------------------------------
// P1: per-row sum-of-squares for the three weight matrices (Frobenius norms)
// Deterministic: fixed strided accumulation + fixed smem tree.
// ---------------------------------------------------------------------------
__global__ void p1_rowss(const float* __restrict__ wbb, const float* __restrict__ wff,
                         const float* __restrict__ wll, const float* __restrict__ sc)
{
    int i = blockIdx.x;
    int t = threadIdx.x;  // 128 threads
    float sb = 0.f, sf = 0.f, sl = 0.f;
    for (int j = t; j < NODE; j += 128) {
        float scij = sc[i * NODE + j];
        float wb = expf(wbb[i * NODE + j]) * scij;
        float wf = expf(wff[i * NODE + j]) * scij;
        float wl = 0.5f * (expf(wll[i * NODE + j]) * scij +
                           expf(wll[j * NODE + i]) * sc[j * NODE + i]);
        sb += wb * wb; sf += wf * wf; sl += wl * wl;
    }
    __shared__ float rb[128], rf[128], rl[128];
    rb[t] = sb; rf[t] = sf; rl[t] = sl;
    __syncthreads();
    for (int off = 64; off; off >>= 1) {
        if (t < off) { rb[t] += rb[t + off]; rf[t] += rf[t + off]; rl[t] += rl[t + off]; }
        __syncthreads();
    }
    if (t == 0) {
        g_rowSS[0 * NODE + i] = rb[0];
        g_rowSS[1 * NODE + i] = rf[0];
        g_rowSS[2 * NODE + i] = rl[0];
    }
}

// ---------------------------------------------------------------------------
// P2: finish norms, compute lm column means, reset g_dmax
// ---------------------------------------------------------------------------
__global__ void p2_norms(const float* __restrict__ lm)
{
    int t = threadIdx.x;  // 512 threads, 1 block
    __shared__ float red[512];
    for (int c = 0; c < 3; c++) {
        float s = 0.f;
        for (int i = t; i < NODE; i += 512) s += g_rowSS[c * NODE + i];
        red[t] = s;
        __syncthreads();
        for (int off = 256; off; off >>= 1) {
            if (t < off) red[t] += red[t + off];
            __syncthreads();
        }
        if (t == 0) g_invnorm[c] = 1.0f / sqrtf(red[0]);
        __syncthreads();
    }
    if (t < NODE) {
        float s = 0.f;
        for (int o = 0; o < OUTN; o++) s += lm[o * NODE + t];
        g_colmean[t] = s * (1.0f / OUTN);
    }
    if (t == 0) g_dmax = 0;
}

// ---------------------------------------------------------------------------
// P3: per-node delay histograms K[d] (raw, unnormalized), row sums, dmax.
// One warp per node. Each lane owns bins with (d & 31) == lane -> deterministic.
// ---------------------------------------------------------------------------
__global__ void __launch_bounds__(32) p3_hist(
    const float* __restrict__ wbb, const float* __restrict__ wff,
    const float* __restrict__ wll, const float* __restrict__ sc,
    const float* __restrict__ dist, const float* __restrict__ theta)
{
    int i = blockIdx.x;
    int lane = threadIdx.x;
    __shared__ float4 Ksm[BUF];
    for (int d = lane; d < BUF; d += 32) Ksm[d] = make_float4(0.f, 0.f, 0.f, 0.f);
    __syncthreads();

    float mu = 0.1f + reluf(theta[20]);
    float rsb = 0.f, rsf = 0.f, rsl = 0.f;
    int dmx = 0;
    for (int j = 0; j < NODE; j++) {
        float scij = sc[i * NODE + j];
        float wb = expf(wbb[i * NODE + j]) * scij;
        float wf = expf(wff[i * NODE + j]) * scij;
        float wl = 0.5f * (expf(wll[i * NODE + j]) * scij +
                           expf(wll[j * NODE + i]) * sc[j * NODE + i]);
        int d = (int)(dist[i * NODE + j] / mu);   // truncation toward zero, like astype(int32)
        if (d < 0) d = 0;
        if (d > DMAXC - 1) d = DMAXC - 1;
        if ((j & 31) == lane) { rsb += wb; rsf += wf; rsl += wl; }
        if ((d & 31) == lane) {
            Ksm[d].x += wb; Ksm[d].y += wf; Ksm[d].z += wl;
            dmx = max(dmx, d);
        }
    }
#pragma unroll
    for (int off = 16; off; off >>= 1) {
        rsb += __shfl_xor_sync(0xffffffffu, rsb, off);
        rsf += __shfl_xor_sync(0xffffffffu, rsf, off);
        rsl += __shfl_xor_sync(0xffffffffu, rsl, off);
        dmx = max(dmx, __shfl_xor_sync(0xffffffffu, dmx, off));
    }
    if (lane == 0) {
        g_rs[i * 3 + 0] = rsb;
        g_rs[i * 3 + 1] = rsf;
        g_rs[i * 3 + 2] = rsl;
        atomicMax(&g_dmax, dmx);   // int max: order-independent -> deterministic
    }
    __syncthreads();
    float4* Kg = g_K4 + (size_t)i * BUF;
    for (int d = lane; d < BUF; d += 32) Kg[d] = Ksm[d];
}

// ---------------------------------------------------------------------------
// SIM: one warp per node, 400 serial steps. hE history = 512-slot circular
// buffer in smem; K tile in smem (float4). State kept redundantly in all lanes.
// ---------------------------------------------------------------------------
__global__ void __launch_bounds__(32) sim_kernel(
    const float* __restrict__ ext, const float* __restrict__ hx,
    const float* __restrict__ hE0, const float* __restrict__ theta)
{
    int i = blockIdx.x;
    int lane = threadIdx.x;
    __shared__ float4 Ksm[BUF];
    __shared__ float  B[BUF];

    const float4* Kg = g_K4 + (size_t)i * BUF;
    for (int d = lane; d < BUF; d += 32) Ksm[d] = Kg[d];
    for (int d = lane; d < DMAXC; d += 32) B[d] = hE0[i * DMAXC + d];
    if (lane < BUF - DMAXC) B[DMAXC + lane] = 0.f;

    // scalar parameters (broadcast loads)
    float VL = reluf(theta[0]), VI = reluf(theta[1]), VE = reluf(theta[2]), VN = reluf(theta[3]);
    float amg = reluf(theta[4]), VR = reluf(theta[5]), ps = reluf(theta[6]);
    float gL = reluf(theta[7]), invC = 1.0f / reluf(theta[8]), kap = reluf(theta[9]);
    float ggE = reluf(theta[10]), ggEsc = reluf(theta[11]);
    float ggI = reluf(theta[12]), ggIsc = reluf(theta[13]);
    float ggN = reluf(theta[14]), ggNsc = reluf(theta[15]);
    float gk  = reluf(theta[16]);
    float kki = reluf(theta[21]) * theta[23];
    float g_lc = reluf(theta[24]), g_fc = reluf(theta[25]), g_bc = reluf(theta[26]);

    float invB = g_invnorm[0], invF = g_invnorm[1], invL = g_invnorm[2];
    float AB = g_bc * invB, BB = AB * g_rs[i * 3 + 0];
    float AF = g_fc * invF, BF = AF * g_rs[i * 3 + 1];
    float AL = g_lc * invL, BL = AL * g_rs[i * 3 + 2];
    int kmax = (g_dmax >> 5) + 1;

    // state (pop-major: hx[i][p][state], state 0..3 = V,gE,gI,gN)
    float V0 = hx[i*12 + 0], gE0 = hx[i*12 + 1], gI0 = hx[i*12 + 2], gN0 = hx[i*12 + 3];
    float V1 = hx[i*12 + 4], gE1 = hx[i*12 + 5], gI1 = hx[i*12 + 6], gN1 = hx[i*12 + 7];
    float V2 = hx[i*12 + 8], gE2 = hx[i*12 + 9], gI2 = hx[i*12 +10], gN2 = hx[i*12 +11];

    float dtk = DTF * kap;
    const float* exti = ext + (size_t)i * (STEPS * TRS);
    __syncthreads();

    int t = 0;
    for (int tr = 0; tr < TRS; tr++) {
        for (int st = 0; st < STEPS; st++) {
            // sigmoids of OLD V
            float s0 = 1.0f / (1.0f + expf(-ps * (V0 - VR)));
            float s1 = 1.0f / (1.0f + expf(-ps * (V1 - VR)));
            float s2 = 1.0f / (1.0f + expf(-ps * (V2 - VR)));

            // delayed-history dot products (3 channels share the history load)
            int base = (-t) & (BUF - 1);
            float aB = 0.f, aF = 0.f, aL = 0.f;
#pragma unroll 4
            for (int kk = 0; kk < kmax; kk++) {
                int d = lane + (kk << 5);
                float h = B[(base + d) & (BUF - 1)];
                float4 Kv = Ksm[d];
                aB = fmaf(Kv.x, h, aB);
                aF = fmaf(Kv.y, h, aF);
                aL = fmaf(Kv.z, h, aL);
            }
#pragma unroll
            for (int off = 16; off; off >>= 1) {
                aB += __shfl_xor_sync(0xffffffffu, aB, off);
                aF += __shfl_xor_sync(0xffffffffu, aF, off);
                aL += __shfl_xor_sync(0xffffffffu, aL, off);
            }

            // state math independent of the reduction (overlaps SHFL latency)
            float mN0 = 1.0f / (1.0f + 0.2f * expf(-amg * V0));
            float mN1 = 1.0f / (1.0f + 0.2f * expf(-amg * V1));
            float mN2 = 1.0f / (1.0f + 0.2f * expf(-amg * V2));
            float dV0 = (gL*(-VL - V0) + gE0*(VE - V0) + gI0*(-VI - V0) + gN0*mN0*(VN - V0)) * invC;
            float dV1 = (gL*(-VL - V1) + gE1*(VE - V1) + gI1*(-VI - V1) + gN1*mN1*(VN - V1)) * invC;
            float dV2 = (gL*(-VL - V2) + gE2*(VE - V2) + gI2*(-VI - V2) + gN2*mN2*(VN - V2)) * invC;
            float u = kki * exti[st * TRS + tr];

            float lrB = AB * aB - BB * s2;
            float lrF = AF * aF - BF * s2;
            float lrL = AL * aL - BL * s2;

            float exc0 = ggE  * s2 + lrL + u;
            float exc1 = ggEsc* s0 + lrB;
            float exc2 = gk   * s0 + lrF + u;
            float inh0 = ggI  * s1;
            float inh1 = ggIsc* s1;
            float inh2 = ggI  * s1;
            float nm0  = ggN  * s2 + lrL;
            float nm1  = ggNsc* s0;
            float nm2  = ggN  * s0;

            V0 += DTF * dV0;  V1 += DTF * dV1;  V2 += DTF * dV2;
            gE0 += dtk * (exc0 - gE0); gE1 += dtk * (exc1 - gE1); gE2 += dtk * (exc2 - gE2);
            gI0 += dtk * (inh0 - gI0); gI1 += dtk * (inh1 - gI1); gI2 += dtk * (inh2 - gI2);
            gN0 += dtk * (nm0  - gN0); gN1 += dtk * (nm1  - gN1); gN2 += dtk * (nm2  - gN2);

            if (lane == 0) B[(base - 1) & (BUF - 1)] = s2;  // push sP(t)
            __syncwarp();
            t++;
        }
        if (lane == 0) g_Vsnap[tr * NODE + i] = V2;  // V[:,2] after 10 steps
    }
}

// ---------------------------------------------------------------------------
// EEG: out[tr,o] = cy0 * (dot(lm[o]-colmean, Vsnap[tr]) ) - y0
// ---------------------------------------------------------------------------
__global__ void eeg_kernel(const float* __restrict__ lm, const float* __restrict__ theta,
                           float* __restrict__ out)
{
    int tr = blockIdx.x;
    int o  = threadIdx.x;  // 64
    __shared__ float Vs[NODE];
    __shared__ float red[64];
    for (int i = o; i < NODE; i += 64) Vs[i] = g_Vsnap[tr * NODE + i];
    __syncthreads();
    float pm = 0.f;
    for (int i = o; i < NODE; i += 64) pm += g_colmean[i] * Vs[i];
    red[o] = pm;
    __syncthreads();
    for (int off = 32; off; off >>= 1) {
        if (o < off) red[o] += red[o + off];
        __syncthreads();
    }
    float m = red[0];
    float acc = 0.f;
#pragma unroll 8
    for (int i = 0; i < NODE; i++) acc = fmaf(lm[o * NODE + i], Vs[i], acc);
    float cy0 = theta[22], y0v = theta[19];
    out[tr * OUTN + o] = cy0 * (acc - m) - y0v;
}

// ---------------------------------------------------------------------------
extern "C" void kernel_launch(void* const* d_in, const int* in_sizes, int n_in,
                              void* d_out, int out_size)
{
    const float* ext   = (const float*)d_in[0];
    const float* hx    = (const float*)d_in[1];
    const float* hE    = (const float*)d_in[2];
    const float* sc    = (const float*)d_in[3];
    const float* dist  = (const float*)d_in[4];
    const float* wbb   = (const float*)d_in[5];
    const float* wff   = (const float*)d_in[6];
    const float* wll   = (const float*)d_in[7];
    const float* lm    = (const float*)d_in[8];
    const float* theta = (const float*)d_in[9];
    float* out = (float*)d_out;

    p1_rowss<<<NODE, 128>>>(wbb, wff, wll, sc);
    p2_norms<<<1, 512>>>(lm);
    p3_hist<<<NODE, 32>>>(wbb, wff, wll, sc, dist, theta);
    sim_kernel<<<NODE, 32>>>(ext, hx, hE, theta);
    eeg_kernel<<<TRS, OUTN>>>(lm, theta, out);
}

// round 2
// speedup vs baseline: 1.2609x; 1.2609x over previous
#include <cuda_runtime.h>
#include <math.h>

#define NODE  400
#define TRS   40
#define STEPS 10
#define NSTEP (TRS * STEPS)
#define OUTN  64
#define DMAXC 500
#define BUF   512
#define ACCN  1024
#define DTF   0.1f

// ---- persistent scratch (device globals; no allocation) ----
__device__ float  g_rowSS[3 * NODE];
__device__ float  g_invnorm[3];       // [b, f, l]
__device__ float  g_rs[NODE * 3];     // raw row sums [b,f,l] per node
__device__ float4 g_K4[NODE * BUF];   // per-node delay histogram (x=b,y=f,z=l)
__device__ int    g_dmax;
__device__ float  g_colmean[NODE];
__device__ float  g_Vsnap[TRS * NODE];

__device__ __forceinline__ float reluf(float x) { return x > 0.f ? x : 0.f; }

// ---------------------------------------------------------------------------
// P1: per-row sum-of-squares for the three weight matrices (Frobenius norms)
// ---------------------------------------------------------------------------
__global__ void p1_rowss(const float* __restrict__ wbb, const float* __restrict__ wff,
                         const float* __restrict__ wll, const float* __restrict__ sc)
{
    int i = blockIdx.x;
    int t = threadIdx.x;  // 128 threads
    float sb = 0.f, sf = 0.f, sl = 0.f;
    for (int j = t; j < NODE; j += 128) {
        float scij = sc[i * NODE + j];
        float wb = __expf(wbb[i * NODE + j]) * scij;
        float wf = __expf(wff[i * NODE + j]) * scij;
        float wl = 0.5f * (__expf(wll[i * NODE + j]) * scij +
                           __expf(wll[j * NODE + i]) * sc[j * NODE + i]);
        sb += wb * wb; sf += wf * wf; sl += wl * wl;
    }
    __shared__ float rb[128], rf[128], rl[128];
    rb[t] = sb; rf[t] = sf; rl[t] = sl;
    __syncthreads();
    for (int off = 64; off; off >>= 1) {
        if (t < off) { rb[t] += rb[t + off]; rf[t] += rf[t + off]; rl[t] += rl[t + off]; }
        __syncthreads();
    }
    if (t == 0) {
        g_rowSS[0 * NODE + i] = rb[0];
        g_rowSS[1 * NODE + i] = rf[0];
        g_rowSS[2 * NODE + i] = rl[0];
    }
}

// ---------------------------------------------------------------------------
// P2: finish norms, lm column means, reset g_dmax
// ---------------------------------------------------------------------------
__global__ void p2_norms(const float* __restrict__ lm)
{
    int t = threadIdx.x;  // 512 threads, 1 block
    __shared__ float red[512];
    for (int c = 0; c < 3; c++) {
        float s = 0.f;
        for (int i = t; i < NODE; i += 512) s += g_rowSS[c * NODE + i];
        red[t] = s;
        __syncthreads();
        for (int off = 256; off; off >>= 1) {
            if (t < off) red[t] += red[t + off];
            __syncthreads();
        }
        if (t == 0) g_invnorm[c] = 1.0f / sqrtf(red[0]);
        __syncthreads();
    }
    if (t < NODE) {
        float s = 0.f;
        for (int o = 0; o < OUTN; o++) s += lm[o * NODE + t];
        g_colmean[t] = s * (1.0f / OUTN);
    }
    if (t == 0) g_dmax = 0;
}

// ---------------------------------------------------------------------------
// P3: per-node delay histograms, row sums, dmax. 4 warps per node, each warp
// owns 100 j's with a private smem histogram; deterministic fixed-order merge.
// ---------------------------------------------------------------------------
__global__ void __launch_bounds__(128) p3_hist(
    const float* __restrict__ wbb, const float* __restrict__ wff,
    const float* __restrict__ wll, const float* __restrict__ sc,
    const float* __restrict__ dist, const float* __restrict__ theta)
{
    int i = blockIdx.x;
    int tid = threadIdx.x;
    int w = tid >> 5, lane = tid & 31;
    __shared__ float4 H[4][BUF];    // 32 KB private histograms
    __shared__ float  rs_s[4][3];
    for (int d = tid; d < BUF; d += 128) {
        float4 z = make_float4(0.f, 0.f, 0.f, 0.f);
        H[0][d] = z; H[1][d] = z; H[2][d] = z; H[3][d] = z;
    }
    __syncthreads();

    float mu = 0.1f + reluf(theta[20]);
    float rsb = 0.f, rsf = 0.f, rsl = 0.f;
    int dmx = 0;
    int j0 = w * (NODE / 4);
    for (int jj = 0; jj < NODE / 4; jj++) {
        int j = j0 + jj;
        float scij = sc[i * NODE + j];
        float wb = __expf(wbb[i * NODE + j]) * scij;
        float wf = __expf(wff[i * NODE + j]) * scij;
        float wl = 0.5f * (__expf(wll[i * NODE + j]) * scij +
                           __expf(wll[j * NODE + i]) * sc[j * NODE + i]);
        int d = (int)(dist[i * NODE + j] / mu);   // exact: division like reference
        if (d < 0) d = 0;
        if (d > DMAXC - 1) d = DMAXC - 1;
        if ((jj & 31) == lane) { rsb += wb; rsf += wf; rsl += wl; }
        if ((d & 31) == lane) {
            H[w][d].x += wb; H[w][d].y += wf; H[w][d].z += wl;
            dmx = max(dmx, d);
        }
    }
#pragma unroll
    for (int off = 16; off; off >>= 1) {
        rsb += __shfl_xor_sync(0xffffffffu, rsb, off);
        rsf += __shfl_xor_sync(0xffffffffu, rsf, off);
        rsl += __shfl_xor_sync(0xffffffffu, rsl, off);
        dmx = max(dmx, __shfl_xor_sync(0xffffffffu, dmx, off));
    }
    if (lane == 0) {
        rs_s[w][0] = rsb; rs_s[w][1] = rsf; rs_s[w][2] = rsl;
        atomicMax(&g_dmax, dmx);   // int max: order-independent
    }
    __syncthreads();

    float4* Kg = g_K4 + (size_t)i * BUF;
    for (int d = tid; d < BUF; d += 128) {
        float4 a = H[0][d], b = H[1][d], c = H[2][d], e = H[3][d];
        float4 r;
        r.x = ((a.x + b.x) + c.x) + e.x;
        r.y = ((a.y + b.y) + c.y) + e.y;
        r.z = ((a.z + b.z) + c.z) + e.z;
        r.w = 0.f;
        Kg[d] = r;
    }
    if (tid == 0) {
        g_rs[i * 3 + 0] = ((rs_s[0][0] + rs_s[1][0]) + rs_s[2][0]) + rs_s[3][0];
        g_rs[i * 3 + 1] = ((rs_s[0][1] + rs_s[1][1]) + rs_s[2][1]) + rs_s[3][1];
        g_rs[i * 3 + 2] = ((rs_s[0][2] + rs_s[1][2]) + rs_s[2][2]) + rs_s[3][2];
    }
}

// ---------------------------------------------------------------------------
// SIM: one warp per node. Scatter-forward accumulators: pushing s2(t) scatters
// K[d]*s2(t) into Acc[t+1+d] (lane-owned slots, conflict-free). Per-step dot
// = 3 broadcast LDS reads; no warp reduction. Initial history pre-folded.
// ---------------------------------------------------------------------------
__global__ void __launch_bounds__(32) sim_kernel(
    const float* __restrict__ ext, const float* __restrict__ hx,
    const float* __restrict__ hE0, const float* __restrict__ theta)
{
    int i = blockIdx.x;
    int lane = threadIdx.x;
    __shared__ float4 Ksm[BUF];                   // 8 KB
    __shared__ float  AccB[ACCN], AccF[ACCN], AccL[ACCN];  // 12 KB
    __shared__ float  Es[NSTEP];                  // 1.6 KB
    __shared__ float  H0[BUF];                    // 2 KB

    const float4* Kg = g_K4 + (size_t)i * BUF;
    for (int d = lane; d < BUF; d += 32) Ksm[d] = Kg[d];
    for (int d = lane; d < DMAXC; d += 32) H0[d] = hE0[i * DMAXC + d];
    for (int d = DMAXC + lane; d < BUF; d += 32) H0[d] = 0.f;
    for (int s = lane; s < ACCN; s += 32) { AccB[s] = 0.f; AccF[s] = 0.f; AccL[s] = 0.f; }
    for (int s = lane; s < NSTEP; s += 32) Es[s] = ext[(size_t)i * NSTEP + s];
    __syncwarp();

    int dmax = g_dmax;
    // fold initial history: Acc[tau] = sum_{d>=tau} K[d] * hE0[d-tau]
    for (int tau = lane; tau <= dmax && tau < NSTEP; tau += 32) {
        float aB = 0.f, aF = 0.f, aL = 0.f;
        for (int d = tau; d <= dmax; d++) {
            float h = H0[d - tau];
            float4 Kv = Ksm[d];
            aB = fmaf(Kv.x, h, aB);
            aF = fmaf(Kv.y, h, aF);
            aL = fmaf(Kv.z, h, aL);
        }
        AccB[tau] = aB; AccF[tau] = aF; AccL[tau] = aL;
    }
    __syncwarp();

    // time-invariant taps for d in [0,128) live in registers
    float4 K0 = Ksm[lane], K1 = Ksm[lane + 32], K2 = Ksm[lane + 64], K3 = Ksm[lane + 96];
    bool tail = (dmax >= 128);

    // scalar parameters
    float VL = reluf(theta[0]), VI = reluf(theta[1]), VE = reluf(theta[2]), VN = reluf(theta[3]);
    float amg = reluf(theta[4]), VR = reluf(theta[5]), ps = reluf(theta[6]);
    float gL = reluf(theta[7]), invC = __fdividef(1.0f, reluf(theta[8])), kap = reluf(theta[9]);
    float ggE = reluf(theta[10]), ggEsc = reluf(theta[11]);
    float ggI = reluf(theta[12]), ggIsc = reluf(theta[13]);
    float ggN = reluf(theta[14]), ggNsc = reluf(theta[15]);
    float gk  = reluf(theta[16]);
    float kki = reluf(theta[21]) * theta[23];
    float g_lc = reluf(theta[24]), g_fc = reluf(theta[25]), g_bc = reluf(theta[26]);

    float AB = g_bc * g_invnorm[0], BB = AB * g_rs[i * 3 + 0];
    float AF = g_fc * g_invnorm[1], BF = AF * g_rs[i * 3 + 1];
    float AL = g_lc * g_invnorm[2], BL = AL * g_rs[i * 3 + 2];

    float V0 = hx[i*12 + 0], gE0 = hx[i*12 + 1], gI0 = hx[i*12 + 2], gN0 = hx[i*12 + 3];
    float V1 = hx[i*12 + 4], gE1 = hx[i*12 + 5], gI1 = hx[i*12 + 6], gN1 = hx[i*12 + 7];
    float V2 = hx[i*12 + 8], gE2 = hx[i*12 + 9], gI2 = hx[i*12 +10], gN2 = hx[i*12 +11];

    float dtk = DTF * kap;
    int t = 0;
    for (int tr = 0; tr < TRS; tr++) {
#pragma unroll
        for (int st = 0; st < STEPS; st++) {
            // sigmoids of OLD V (fast exp + fast rcp)
            float s0 = __fdividef(1.0f, 1.0f + __expf(-ps * (V0 - VR)));
            float s1 = __fdividef(1.0f, 1.0f + __expf(-ps * (V1 - VR)));
            float s2 = __fdividef(1.0f, 1.0f + __expf(-ps * (V2 - VR)));

            // delayed long-range sums: single broadcast read per channel
            float aB = AccB[t], aF = AccF[t], aL = AccL[t];

            float mN0 = __fdividef(1.0f, 1.0f + 0.2f * __expf(-amg * V0));
            float mN1 = __fdividef(1.0f, 1.0f + 0.2f * __expf(-amg * V1));
            float mN2 = __fdividef(1.0f, 1.0f + 0.2f * __expf(-amg * V2));
            float dV0 = (gL*(-VL - V0) + gE0*(VE - V0) + gI0*(-VI - V0) + gN0*mN0*(VN - V0)) * invC;
            float dV1 = (gL*(-VL - V1) + gE1*(VE - V1) + gI1*(-VI - V1) + gN1*mN1*(VN - V1)) * invC;
            float dV2 = (gL*(-VL - V2) + gE2*(VE - V2) + gI2*(-VI - V2) + gN2*mN2*(VN - V2)) * invC;
            float u = kki * Es[st * TRS + tr];

            float lrB = AB * aB - BB * s2;
            float lrF = AF * aF - BF * s2;
            float lrL = AL * aL - BL * s2;

            float exc0 = ggE  * s2 + lrL + u;
            float exc1 = ggEsc* s0 + lrB;
            float exc2 = gk   * s0 + lrF + u;
            float nm0  = ggN  * s2 + lrL;
            float nm1  = ggNsc* s0;
            float nm2  = ggN  * s0;

            V0 += DTF * dV0;  V1 += DTF * dV1;  V2 += DTF * dV2;
            gE0 += dtk * (exc0 - gE0); gE1 += dtk * (exc1 - gE1); gE2 += dtk * (exc2 - gE2);
            gI0 += dtk * (ggI  * s1 - gI0);
            gI1 += dtk * (ggIsc* s1 - gI1);
            gI2 += dtk * (ggI  * s1 - gI2);
            gN0 += dtk * (nm0  - gN0); gN1 += dtk * (nm1  - gN1); gN2 += dtk * (nm2  - gN2);

            // scatter s2(t) into future accumulator slots (lane-owned, no conflicts)
            int sb = t + 1 + lane;
            AccB[sb      ] = fmaf(K0.x, s2, AccB[sb      ]);
            AccF[sb      ] = fmaf(K0.y, s2, AccF[sb      ]);
            AccL[sb      ] = fmaf(K0.z, s2, AccL[sb      ]);
            AccB[sb +  32] = fmaf(K1.x, s2, AccB[sb +  32]);
            AccF[sb +  32] = fmaf(K1.y, s2, AccF[sb +  32]);
            AccL[sb +  32] = fmaf(K1.z, s2, AccL[sb +  32]);
            AccB[sb +  64] = fmaf(K2.x, s2, AccB[sb +  64]);
            AccF[sb +  64] = fmaf(K2.y, s2, AccF[sb +  64]);
            AccL[sb +  64] = fmaf(K2.z, s2, AccL[sb +  64]);
            AccB[sb +  96] = fmaf(K3.x, s2, AccB[sb +  96]);
            AccF[sb +  96] = fmaf(K3.y, s2, AccF[sb +  96]);
            AccL[sb +  96] = fmaf(K3.z, s2, AccL[sb +  96]);
            if (tail) {
                for (int d = 128 + lane; d <= dmax; d += 32) {
                    float4 Kv = Ksm[d];
                    int s = t + 1 + d;
                    AccB[s] = fmaf(Kv.x, s2, AccB[s]);
                    AccF[s] = fmaf(Kv.y, s2, AccF[s]);
                    AccL[s] = fmaf(Kv.z, s2, AccL[s]);
                }
            }
            __syncwarp();
            t++;
        }
        if (lane == 0) g_Vsnap[tr * NODE + i] = V2;
    }
}

// ---------------------------------------------------------------------------
// EEG: out[tr,o] = cy0 * dot(lm[o]-colmean, Vsnap[tr]) - y0
// ---------------------------------------------------------------------------
__global__ void eeg_kernel(const float* __restrict__ lm, const float* __restrict__ theta,
                           float* __restrict__ out)
{
    int tr = blockIdx.x;
    int o  = threadIdx.x;  // 64
    __shared__ float Vs[NODE];
    __shared__ float red[64];
    for (int i = o; i < NODE; i += 64) Vs[i] = g_Vsnap[tr * NODE + i];
    __syncthreads();
    float pm = 0.f;
    for (int i = o; i < NODE; i += 64) pm += g_colmean[i] * Vs[i];
    red[o] = pm;
    __syncthreads();
    for (int off = 32; off; off >>= 1) {
        if (o < off) red[o] += red[o + off];
        __syncthreads();
    }
    float m = red[0];
    float acc = 0.f;
#pragma unroll 8
    for (int i = 0; i < NODE; i++) acc = fmaf(lm[o * NODE + i], Vs[i], acc);
    float cy0 = theta[22], y0v = theta[19];
    out[tr * OUTN + o] = cy0 * (acc - m) - y0v;
}

// ---------------------------------------------------------------------------
extern "C" void kernel_launch(void* const* d_in, const int* in_sizes, int n_in,
                              void* d_out, int out_size)
{
    const float* ext   = (const float*)d_in[0];
    const float* hx    = (const float*)d_in[1];
    const float* hE    = (const float*)d_in[2];
    const float* sc    = (const float*)d_in[3];
    const float* dist  = (const float*)d_in[4];
    const float* wbb   = (const float*)d_in[5];
    const float* wff   = (const float*)d_in[6];
    const float* wll   = (const float*)d_in[7];
    const float* lm    = (const float*)d_in[8];
    const float* theta = (const float*)d_in[9];
    float* out = (float*)d_out;

    p1_rowss<<<NODE, 128>>>(wbb, wff, wll, sc);
    p2_norms<<<1, 512>>>(lm);
    p3_hist<<<NODE, 128>>>(wbb, wff, wll, sc, dist, theta);
    sim_kernel<<<NODE, 32>>>(ext, hx, hE, theta);
    eeg_kernel<<<TRS, OUTN>>>(lm, theta, out);
}

// round 3
// speedup vs baseline: 1.8009x; 1.4282x over previous
#include <cuda_runtime.h>
#include <math.h>

#define NODE  400
#define TRS   40
#define STEPS 10
#define NSTEP (TRS * STEPS)
#define OUTN  64
#define DMAXC 500
#define KBUF  512
#define ACCN  544      // >= NSTEP + 128 + 1
#define DTF   0.1f
#define LOG2E 1.4426950408889634f

// ---- persistent scratch (device globals; no allocation) ----
__device__ float  g_rowSS[3 * NODE];
__device__ float  g_invnorm[3];       // [b, f, l]
__device__ float  g_rs[NODE * 3];     // raw row sums [b,f,l] per node
__device__ float4 g_K4[NODE * KBUF];  // per-node delay histogram (x=b,y=f,z=l)
__device__ int    g_ndmax[NODE];
__device__ float  g_colmean[NODE];
__device__ float  g_Vsnap[TRS * NODE];

__device__ __forceinline__ float reluf(float x) { return x > 0.f ? x : 0.f; }
__device__ __forceinline__ float ex2f(float x) { float y; asm("ex2.approx.f32 %0,%1;" : "=f"(y) : "f"(x)); return y; }
__device__ __forceinline__ float rcpf(float x) { float y; asm("rcp.approx.f32 %0,%1;" : "=f"(y) : "f"(x)); return y; }

// ---------------------------------------------------------------------------
// PREP: per-node weights, row sums, row sum-of-squares, delay histogram, dmax.
// One block of 128 threads per node; j-parallel; deterministic fixed trees.
// ---------------------------------------------------------------------------
__global__ void __launch_bounds__(128) prep_kernel(
    const float* __restrict__ wbb, const float* __restrict__ wff,
    const float* __restrict__ wll, const float* __restrict__ sc,
    const float* __restrict__ dist, const float* __restrict__ theta)
{
    int i = blockIdx.x;
    int tid = threadIdx.x;
    __shared__ float4 w4[NODE];
    __shared__ int    dly[NODE];
    __shared__ float  red[6][128];
    __shared__ int    dred[4];

    float mu = 0.1f + reluf(theta[20]);
    float ssb = 0.f, ssf = 0.f, ssl = 0.f, rb = 0.f, rf = 0.f, rl = 0.f;
    for (int j = tid; j < NODE; j += 128) {
        float scij = sc[i * NODE + j];
        float wb = __expf(wbb[i * NODE + j]) * scij;
        float wf = __expf(wff[i * NODE + j]) * scij;
        float wl = 0.5f * (__expf(wll[i * NODE + j]) * scij +
                           __expf(wll[j * NODE + i]) * sc[j * NODE + i]);
        int d = (int)(dist[i * NODE + j] / mu);   // accurate division like reference
        if (d < 0) d = 0;
        if (d > DMAXC - 1) d = DMAXC - 1;
        w4[j] = make_float4(wb, wf, wl, 0.f);
        dly[j] = d;
        ssb += wb * wb; ssf += wf * wf; ssl += wl * wl;
        rb += wb; rf += wf; rl += wl;
    }
    red[0][tid] = ssb; red[1][tid] = ssf; red[2][tid] = ssl;
    red[3][tid] = rb;  red[4][tid] = rf;  red[5][tid] = rl;
    __syncthreads();
    for (int off = 64; off; off >>= 1) {
        if (tid < off) {
#pragma unroll
            for (int c = 0; c < 6; c++) red[c][tid] += red[c][tid + off];
        }
        __syncthreads();
    }
    if (tid == 0) {
        g_rowSS[0 * NODE + i] = red[0][0];
        g_rowSS[1 * NODE + i] = red[1][0];
        g_rowSS[2 * NODE + i] = red[2][0];
        g_rs[i * 3 + 0] = red[3][0];
        g_rs[i * 3 + 1] = red[4][0];
        g_rs[i * 3 + 2] = red[5][0];
    }

    // histogram: thread owns bins d with (d & 127) == tid (4 slots in registers)
    float b0=0,f0=0,l0=0, b1=0,f1=0,l1=0, b2=0,f2=0,l2=0, b3=0,f3=0,l3=0;
    int dmx = 0;
    for (int j = 0; j < NODE; j++) {
        int d = dly[j];
        if ((d & 127) == tid) {
            float4 w = w4[j];
            int s = d >> 7;
            if      (s == 0) { b0 += w.x; f0 += w.y; l0 += w.z; }
            else if (s == 1) { b1 += w.x; f1 += w.y; l1 += w.z; }
            else if (s == 2) { b2 += w.x; f2 += w.y; l2 += w.z; }
            else             { b3 += w.x; f3 += w.y; l3 += w.z; }
            dmx = d > dmx ? d : dmx;
        }
    }
    float4* Kg = g_K4 + (size_t)i * KBUF;
    Kg[tid      ] = make_float4(b0, f0, l0, 0.f);
    Kg[tid + 128] = make_float4(b1, f1, l1, 0.f);
    Kg[tid + 256] = make_float4(b2, f2, l2, 0.f);
    Kg[tid + 384] = make_float4(b3, f3, l3, 0.f);
#pragma unroll
    for (int off = 16; off; off >>= 1) dmx = max(dmx, __shfl_xor_sync(0xffffffffu, dmx, off));
    if ((tid & 31) == 0) dred[tid >> 5] = dmx;
    __syncthreads();
    if (tid == 0) g_ndmax[i] = max(max(dred[0], dred[1]), max(dred[2], dred[3]));
}

// ---------------------------------------------------------------------------
// P2: finish norms + lm column means
// ---------------------------------------------------------------------------
__global__ void p2_norms(const float* __restrict__ lm)
{
    int t = threadIdx.x;  // 512 threads, 1 block
    __shared__ float red[512];
    for (int c = 0; c < 3; c++) {
        float s = 0.f;
        for (int i = t; i < NODE; i += 512) s += g_rowSS[c * NODE + i];
        red[t] = s;
        __syncthreads();
        for (int off = 256; off; off >>= 1) {
            if (t < off) red[t] += red[t + off];
            __syncthreads();
        }
        if (t == 0) g_invnorm[c] = 1.0f / sqrtf(red[0]);
        __syncthreads();
    }
    if (t < NODE) {
        float s = 0.f;
        for (int o = 0; o < OUTN; o++) s += lm[o * NODE + t];
        g_colmean[t] = s * (1.0f / OUTN);
    }
}

// ---------------------------------------------------------------------------
// SIM: one block (128 init threads, 1 persistent warp) per node.
// Populations lane-distributed (pop = lane % 3): 1 sigmoid + 1 mN per lane.
// Scatter-forward conv into float4 Acc (B,F,L packed): 4 RMW groups per step.
// ---------------------------------------------------------------------------
__global__ void __launch_bounds__(128) sim_kernel(
    const float* __restrict__ ext, const float* __restrict__ hx,
    const float* __restrict__ hE0, const float* __restrict__ theta)
{
    int i = blockIdx.x;
    int tid = threadIdx.x;
    __shared__ float4 Ksm[KBUF];   // 8 KB
    __shared__ float4 Acc[ACCN];   // 8.5 KB
    __shared__ float  H0[KBUF];    // 2 KB
    __shared__ float  Es[NSTEP];   // 1.6 KB

    const float4* Kg = g_K4 + (size_t)i * KBUF;
    for (int d = tid; d < KBUF; d += 128) Ksm[d] = Kg[d];
    for (int d = tid; d < DMAXC; d += 128) H0[d] = hE0[i * DMAXC + d];
    if (tid < KBUF - DMAXC) H0[DMAXC + tid] = 0.f;
    for (int s = tid; s < ACCN; s += 128) Acc[s] = make_float4(0.f, 0.f, 0.f, 0.f);
    for (int s = tid; s < NSTEP; s += 128) Es[s] = ext[(size_t)i * NSTEP + s];
    __syncthreads();

    int dmax = g_ndmax[i];
    // fold initial history: Acc[tau] = sum_{d>=tau} K[d] * hE0[d-tau]
    for (int tau = tid; tau <= dmax && tau < NSTEP; tau += 128) {
        float aB = 0.f, aF = 0.f, aL = 0.f;
        for (int d = tau; d <= dmax; d++) {
            float h = H0[d - tau];
            float4 Kv = Ksm[d];
            aB = fmaf(Kv.x, h, aB);
            aF = fmaf(Kv.y, h, aF);
            aL = fmaf(Kv.z, h, aL);
        }
        Acc[tau] = make_float4(aB, aF, aL, 0.f);
    }
    __syncthreads();
    if (tid >= 32) return;   // warps 1-3 done; warp 0 simulates

    int lane = tid;
    int pop = lane % 3;

    // scalar parameters
    float VL = reluf(theta[0]), VI = reluf(theta[1]), VE = reluf(theta[2]), VN = reluf(theta[3]);
    float amg = reluf(theta[4]), VR = reluf(theta[5]), ps = reluf(theta[6]);
    float gL = reluf(theta[7]), invC = rcpf(reluf(theta[8])), kap = reluf(theta[9]);
    float ggE = reluf(theta[10]), ggEsc = reluf(theta[11]);
    float ggI = reluf(theta[12]), ggIsc = reluf(theta[13]);
    float ggN = reluf(theta[14]), ggNsc = reluf(theta[15]);
    float gk  = reluf(theta[16]);
    float kki = reluf(theta[21]) * theta[23];
    float g_lc = reluf(theta[24]), g_fc = reluf(theta[25]), g_bc = reluf(theta[26]);

    float ABc = g_bc * g_invnorm[0], BBc = ABc * g_rs[i * 3 + 0];
    float AFc = g_fc * g_invnorm[1], BFc = AFc * g_rs[i * 3 + 1];
    float ALc = g_lc * g_invnorm[2], BLc = ALc * g_rs[i * 3 + 2];

    // per-lane population constants
    float cE, cI, cN, mU, mLr, Al, Bl;
    if (pop == 0)      { cE = ggE;   cI = ggI;   cN = ggN;   mU = kki; mLr = 1.f; Al = ALc; Bl = BLc; }
    else if (pop == 1) { cE = ggEsc; cI = ggIsc; cN = ggNsc; mU = 0.f; mLr = 0.f; Al = ABc; Bl = BBc; }
    else               { cE = gk;    cI = ggI;   cN = ggN;   mU = kki; mLr = 0.f; Al = AFc; Bl = BFc; }

    // exp arg folding: exp(-ps(V-VR)) = 2^(nps2*V + cs); exp(-amg V) = 2^(namg2*V)
    float nps2 = -ps * LOG2E, cs = ps * VR * LOG2E;
    float namg2 = -amg * LOG2E;

    // per-lane state (its population)
    float V  = hx[i * 12 + pop * 4 + 0];
    float gE = hx[i * 12 + pop * 4 + 1];
    float gI = hx[i * 12 + pop * 4 + 2];
    float gN = hx[i * 12 + pop * 4 + 3];

    // register taps d = lane + 32g, g < 4 (K is zero beyond dmax)
    float4 K0 = Ksm[lane], K1 = Ksm[lane + 32], K2 = Ksm[lane + 64], K3 = Ksm[lane + 96];
    bool tail = (dmax >= 128);

    float dtk = DTF * kap;
    int t = 0;
    for (int tr = 0; tr < TRS; tr++) {
#pragma unroll
        for (int st = 0; st < STEPS; st++) {
            // own-population sigmoid (1 EX2 + 1 RCP per warp-instruction, 3 pops covered)
            float s_ = rcpf(1.0f + ex2f(fmaf(nps2, V, cs)));
            float s0 = __shfl_sync(0xffffffffu, s_, 0);
            float s1 = __shfl_sync(0xffffffffu, s_, 1);
            float s2 = __shfl_sync(0xffffffffu, s_, 2);

            float mN = rcpf(fmaf(0.2f, ex2f(namg2 * V), 1.0f));
            float dV = (fmaf(gL, -VL - V,
                        fmaf(gE, VE - V,
                        fmaf(gI, -VI - V, (gN * mN) * (VN - V))))) * invC;

            float4 a4 = Acc[t];
            float a = (pop == 0) ? a4.z : ((pop == 1) ? a4.x : a4.y);
            float lr = fmaf(Al, a, -(Bl * s2));

            float u = Es[st * TRS + tr];
            float se = (pop == 0) ? s2 : s0;
            float exc = fmaf(cE, se, lr);
            exc = fmaf(mU, u, exc);
            float nm = fmaf(cN, se, mLr * lr);
            float inh = cI * s1;

            V  = fmaf(DTF, dV, V);
            gE = fmaf(dtk, exc - gE, gE);
            gI = fmaf(dtk, inh - gI, gI);
            gN = fmaf(dtk, nm  - gN, gN);

            // scatter s2(t) into future slots (lane-owned, conflict-free)
            int sb = t + 1 + lane;
            float4 A0 = Acc[sb];
            A0.x = fmaf(K0.x, s2, A0.x); A0.y = fmaf(K0.y, s2, A0.y); A0.z = fmaf(K0.z, s2, A0.z);
            Acc[sb] = A0;
            float4 A1 = Acc[sb + 32];
            A1.x = fmaf(K1.x, s2, A1.x); A1.y = fmaf(K1.y, s2, A1.y); A1.z = fmaf(K1.z, s2, A1.z);
            Acc[sb + 32] = A1;
            float4 A2 = Acc[sb + 64];
            A2.x = fmaf(K2.x, s2, A2.x); A2.y = fmaf(K2.y, s2, A2.y); A2.z = fmaf(K2.z, s2, A2.z);
            Acc[sb + 64] = A2;
            float4 A3 = Acc[sb + 96];
            A3.x = fmaf(K3.x, s2, A3.x); A3.y = fmaf(K3.y, s2, A3.y); A3.z = fmaf(K3.z, s2, A3.z);
            Acc[sb + 96] = A3;
            if (tail) {
                for (int d = 128 + lane; d <= dmax; d += 32) {
                    float4 Kv = Ksm[d];
                    float4 Av = Acc[t + 1 + d];
                    Av.x = fmaf(Kv.x, s2, Av.x); Av.y = fmaf(Kv.y, s2, Av.y); Av.z = fmaf(Kv.z, s2, Av.z);
                    Acc[t + 1 + d] = Av;
                }
            }
            __syncwarp();
            t++;
        }
        if (lane == 2) g_Vsnap[tr * NODE + i] = V;   // population 2's V
    }
}

// ---------------------------------------------------------------------------
// EEG: out[tr,o] = cy0 * dot(lm[o]-colmean, Vsnap[tr]) - y0
// ---------------------------------------------------------------------------
__global__ void eeg_kernel(const float* __restrict__ lm, const float* __restrict__ theta,
                           float* __restrict__ out)
{
    int tr = blockIdx.x;
    int o  = threadIdx.x;  // 64
    __shared__ float Vs[NODE];
    __shared__ float red[64];
    for (int i = o; i < NODE; i += 64) Vs[i] = g_Vsnap[tr * NODE + i];
    __syncthreads();
    float pm = 0.f;
    for (int i = o; i < NODE; i += 64) pm += g_colmean[i] * Vs[i];
    red[o] = pm;
    __syncthreads();
    for (int off = 32; off; off >>= 1) {
        if (o < off) red[o] += red[o + off];
        __syncthreads();
    }
    float m = red[0];
    float acc = 0.f;
#pragma unroll 8
    for (int i = 0; i < NODE; i++) acc = fmaf(lm[o * NODE + i], Vs[i], acc);
    float cy0 = theta[22], y0v = theta[19];
    out[tr * OUTN + o] = cy0 * (acc - m) - y0v;
}

// ---------------------------------------------------------------------------
extern "C" void kernel_launch(void* const* d_in, const int* in_sizes, int n_in,
                              void* d_out, int out_size)
{
    const float* ext   = (const float*)d_in[0];
    const float* hx    = (const float*)d_in[1];
    const float* hE    = (const float*)d_in[2];
    const float* sc    = (const float*)d_in[3];
    const float* dist  = (const float*)d_in[4];
    const float* wbb   = (const float*)d_in[5];
    const float* wff   = (const float*)d_in[6];
    const float* wll   = (const float*)d_in[7];
    const float* lm    = (const float*)d_in[8];
    const float* theta = (const float*)d_in[9];
    float* out = (float*)d_out;

    prep_kernel<<<NODE, 128>>>(wbb, wff, wll, sc, dist, theta);
    p2_norms<<<1, 512>>>(lm);
    sim_kernel<<<NODE, 128>>>(ext, hx, hE, theta);
    eeg_kernel<<<TRS, OUTN>>>(lm, theta, out);
}

// round 4
// speedup vs baseline: 3.6891x; 2.0486x over previous
#include <cuda_runtime.h>
#include <math.h>

#define NODE  400
#define TRS   40
#define STEPS 10
#define NSTEP (TRS * STEPS)
#define OUTN  64
#define DMAXC 500
#define KBUF  512
#define ACCN  544      // >= NSTEP + 128 + 1
#define DTF   0.1f
#define LOG2E 1.4426950408889634f

// ---- persistent scratch (device globals; no allocation) ----
__device__ float  g_rowSS[3 * NODE];
__device__ float  g_invnorm[3];       // [b, f, l]
__device__ float  g_rs[NODE * 3];     // raw row sums [b,f,l] per node
__device__ float4 g_K4[NODE * KBUF];  // per-node delay histogram (x=b,y=f,z=l)
__device__ int    g_ndmax[NODE];
__device__ float  g_colmean[NODE];
__device__ float  g_Vsnap[TRS * NODE];

__device__ __forceinline__ float reluf(float x) { return x > 0.f ? x : 0.f; }
__device__ __forceinline__ float ex2f(float x) { float y; asm("ex2.approx.f32 %0,%1;" : "=f"(y) : "f"(x)); return y; }
__device__ __forceinline__ float rcpf(float x) { float y; asm("rcp.approx.f32 %0,%1;" : "=f"(y) : "f"(x)); return y; }

// ---------------------------------------------------------------------------
// PREP: per-node weights, row sums, row sum-of-squares, delay histogram, dmax.
// One block of 128 threads per node. Histogram: 4 warps scan 100 j's each into
// private smem histograms; deterministic fixed-order merge.
// ---------------------------------------------------------------------------
__global__ void __launch_bounds__(128) prep_kernel(
    const float* __restrict__ wbb, const float* __restrict__ wff,
    const float* __restrict__ wll, const float* __restrict__ sc,
    const float* __restrict__ dist, const float* __restrict__ theta)
{
    int i = blockIdx.x;
    int tid = threadIdx.x;
    int w = tid >> 5, lane = tid & 31;
    __shared__ float4 w4[NODE];        // 6.4 KB
    __shared__ int    dly[NODE];       // 1.6 KB
    __shared__ float4 H[4][KBUF];      // 32 KB private histograms
    __shared__ float  red[6][128];     // 3 KB
    __shared__ int    dred[4];

    float mu = 0.1f + reluf(theta[20]);
    float ssb = 0.f, ssf = 0.f, ssl = 0.f, rb = 0.f, rf = 0.f, rl = 0.f;
    for (int j = tid; j < NODE; j += 128) {
        float scij = sc[i * NODE + j];
        float wb = __expf(wbb[i * NODE + j]) * scij;
        float wf = __expf(wff[i * NODE + j]) * scij;
        float wl = 0.5f * (__expf(wll[i * NODE + j]) * scij +
                           __expf(wll[j * NODE + i]) * sc[j * NODE + i]);
        int d = (int)(dist[i * NODE + j] / mu);   // accurate division like reference
        if (d < 0) d = 0;
        if (d > DMAXC - 1) d = DMAXC - 1;
        w4[j] = make_float4(wb, wf, wl, 0.f);
        dly[j] = d;
        ssb += wb * wb; ssf += wf * wf; ssl += wl * wl;
        rb += wb; rf += wf; rl += wl;
    }
    for (int d = tid; d < KBUF; d += 128) {
        float4 z = make_float4(0.f, 0.f, 0.f, 0.f);
        H[0][d] = z; H[1][d] = z; H[2][d] = z; H[3][d] = z;
    }
    red[0][tid] = ssb; red[1][tid] = ssf; red[2][tid] = ssl;
    red[3][tid] = rb;  red[4][tid] = rf;  red[5][tid] = rl;
    __syncthreads();
    for (int off = 64; off; off >>= 1) {
        if (tid < off) {
#pragma unroll
            for (int c = 0; c < 6; c++) red[c][tid] += red[c][tid + off];
        }
        __syncthreads();
    }
    if (tid == 0) {
        g_rowSS[0 * NODE + i] = red[0][0];
        g_rowSS[1 * NODE + i] = red[1][0];
        g_rowSS[2 * NODE + i] = red[2][0];
        g_rs[i * 3 + 0] = red[3][0];
        g_rs[i * 3 + 1] = red[4][0];
        g_rs[i * 3 + 2] = red[5][0];
    }

    // histogram: warp w scans j in [100w, 100w+100); lane owns (d&31)==lane bins
    int dmx = 0;
    int j0 = w * (NODE / 4);
    for (int jj = 0; jj < NODE / 4; jj++) {
        int j = j0 + jj;
        int d = dly[j];
        if ((d & 31) == lane) {
            float4 wv = w4[j];
            H[w][d].x += wv.x; H[w][d].y += wv.y; H[w][d].z += wv.z;
            dmx = d > dmx ? d : dmx;
        }
    }
#pragma unroll
    for (int off = 16; off; off >>= 1) dmx = max(dmx, __shfl_xor_sync(0xffffffffu, dmx, off));
    if (lane == 0) dred[w] = dmx;
    __syncthreads();

    float4* Kg = g_K4 + (size_t)i * KBUF;
    for (int d = tid; d < KBUF; d += 128) {
        float4 a = H[0][d], b = H[1][d], c = H[2][d], e = H[3][d];
        float4 r;
        r.x = ((a.x + b.x) + c.x) + e.x;
        r.y = ((a.y + b.y) + c.y) + e.y;
        r.z = ((a.z + b.z) + c.z) + e.z;
        r.w = 0.f;
        Kg[d] = r;
    }
    if (tid == 0) g_ndmax[i] = max(max(dred[0], dred[1]), max(dred[2], dred[3]));
}

// ---------------------------------------------------------------------------
// P2: finish norms + lm column means
// ---------------------------------------------------------------------------
__global__ void p2_norms(const float* __restrict__ lm)
{
    int t = threadIdx.x;  // 512 threads, 1 block
    __shared__ float red[512];
    for (int c = 0; c < 3; c++) {
        float s = 0.f;
        for (int i = t; i < NODE; i += 512) s += g_rowSS[c * NODE + i];
        red[t] = s;
        __syncthreads();
        for (int off = 256; off; off >>= 1) {
            if (t < off) red[t] += red[t + off];
            __syncthreads();
        }
        if (t == 0) g_invnorm[c] = 1.0f / sqrtf(red[0]);
        __syncthreads();
    }
    if (t < NODE) {
        float s = 0.f;
        for (int o = 0; o < OUTN; o++) s += lm[o * NODE + t];
        g_colmean[t] = s * (1.0f / OUTN);
    }
}

// ---------------------------------------------------------------------------
// SIM: one block (128 init threads, 1 persistent warp) per node.
// Near taps (d<32): rotating register partial window P (lane l holds slot t+l),
// per-lane CONSTANT K[lane]; read = shfl(P,0) + LDS of fold+far accumulator.
// Far taps (d>=32) scatter to smem, read >=33 steps later -> syncwarp per trial.
// ---------------------------------------------------------------------------
__global__ void __launch_bounds__(128) sim_kernel(
    const float* __restrict__ ext, const float* __restrict__ hx,
    const float* __restrict__ hE0, const float* __restrict__ theta)
{
    int i = blockIdx.x;
    int tid = threadIdx.x;
    __shared__ float4 Ksm[KBUF];   // 8 KB
    __shared__ float4 Acc[ACCN];   // 8.5 KB (fold + far runtime)
    __shared__ float  H0[KBUF];    // 2 KB
    __shared__ float  Es[NSTEP];   // 1.6 KB

    const float4* Kg = g_K4 + (size_t)i * KBUF;
    for (int d = tid; d < KBUF; d += 128) Ksm[d] = Kg[d];
    for (int d = tid; d < DMAXC; d += 128) H0[d] = hE0[i * DMAXC + d];
    if (tid < KBUF - DMAXC) H0[DMAXC + tid] = 0.f;
    for (int s = tid; s < ACCN; s += 128) Acc[s] = make_float4(0.f, 0.f, 0.f, 0.f);
    for (int s = tid; s < NSTEP; s += 128) Es[s] = ext[(size_t)i * NSTEP + s];
    __syncthreads();

    int dmax = g_ndmax[i];
    // fold initial history: Acc[tau] = sum_{d>=tau} K[d] * hE0[d-tau]
    for (int tau = tid; tau <= dmax && tau < NSTEP; tau += 128) {
        float aB = 0.f, aF = 0.f, aL = 0.f;
        for (int d = tau; d <= dmax; d++) {
            float h = H0[d - tau];
            float4 Kv = Ksm[d];
            aB = fmaf(Kv.x, h, aB);
            aF = fmaf(Kv.y, h, aF);
            aL = fmaf(Kv.z, h, aL);
        }
        Acc[tau] = make_float4(aB, aF, aL, 0.f);
    }
    __syncthreads();
    if (tid >= 32) return;   // warps 1-3 done; warp 0 simulates

    int lane = tid;
    int pop = lane % 3;

    // scalar parameters
    float VL = reluf(theta[0]), VI = reluf(theta[1]), VE = reluf(theta[2]), VN = reluf(theta[3]);
    float amg = reluf(theta[4]), VR = reluf(theta[5]), ps = reluf(theta[6]);
    float gL = reluf(theta[7]), invC = rcpf(reluf(theta[8])), kap = reluf(theta[9]);
    float ggE = reluf(theta[10]), ggEsc = reluf(theta[11]);
    float ggI = reluf(theta[12]), ggIsc = reluf(theta[13]);
    float ggN = reluf(theta[14]), ggNsc = reluf(theta[15]);
    float gk  = reluf(theta[16]);
    float kki = reluf(theta[21]) * theta[23];
    float g_lc = reluf(theta[24]), g_fc = reluf(theta[25]), g_bc = reluf(theta[26]);

    float ABc = g_bc * g_invnorm[0], BBc = ABc * g_rs[i * 3 + 0];
    float AFc = g_fc * g_invnorm[1], BFc = AFc * g_rs[i * 3 + 1];
    float ALc = g_lc * g_invnorm[2], BLc = ALc * g_rs[i * 3 + 2];

    // per-lane population constants
    float cE, cI, cN, mU, mLr, Al, Bl;
    if (pop == 0)      { cE = ggE;   cI = ggI;   cN = ggN;   mU = kki; mLr = 1.f; Al = ALc; Bl = BLc; }
    else if (pop == 1) { cE = ggEsc; cI = ggIsc; cN = ggNsc; mU = 0.f; mLr = 0.f; Al = ABc; Bl = BBc; }
    else               { cE = gk;    cI = ggI;   cN = ggN;   mU = kki; mLr = 0.f; Al = AFc; Bl = BFc; }

    float nps2 = -ps * LOG2E, cs = ps * VR * LOG2E;
    float namg2 = -amg * LOG2E;

    float V  = hx[i * 12 + pop * 4 + 0];
    float gE = hx[i * 12 + pop * 4 + 1];
    float gI = hx[i * 12 + pop * 4 + 2];
    float gN = hx[i * 12 + pop * 4 + 3];

    // near taps (register, constant per lane) + far taps
    float4 Kn = Ksm[lane];
    float4 K1 = Ksm[lane + 32], K2 = Ksm[lane + 64], K3 = Ksm[lane + 96];
    bool tail = (dmax >= 128);

    float PB = 0.f, PF = 0.f, PL = 0.f;   // near-window partials: lane l = slot t+l
    float dtk = DTF * kap;
    int t = 0;
    for (int tr = 0; tr < TRS; tr++) {
#pragma unroll
        for (int st = 0; st < STEPS; st++) {
            float s_ = rcpf(1.0f + ex2f(fmaf(nps2, V, cs)));
            float s0 = __shfl_sync(0xffffffffu, s_, 0);
            float s1 = __shfl_sync(0xffffffffu, s_, 1);
            float s2 = __shfl_sync(0xffffffffu, s_, 2);

            float mN = rcpf(fmaf(0.2f, ex2f(namg2 * V), 1.0f));
            float dV = (fmaf(gL, -VL - V,
                        fmaf(gE, VE - V,
                        fmaf(gI, -VI - V, (gN * mN) * (VN - V))))) * invC;

            // slot-t value: fold+far (smem) + near partial (lane 0's register)
            float4 fa = Acc[t];
            float aPB = __shfl_sync(0xffffffffu, PB, 0);
            float aPF = __shfl_sync(0xffffffffu, PF, 0);
            float aPL = __shfl_sync(0xffffffffu, PL, 0);
            float a = (pop == 0) ? (fa.z + aPL) : ((pop == 1) ? (fa.x + aPB) : (fa.y + aPF));
            float lr = fmaf(Al, a, -(Bl * s2));

            float u = Es[st * TRS + tr];
            float se = (pop == 0) ? s2 : s0;
            float exc = fmaf(cE, se, lr);
            exc = fmaf(mU, u, exc);
            float nm = fmaf(cN, se, mLr * lr);
            float inh = cI * s1;

            V  = fmaf(DTF, dV, V);
            gE = fmaf(dtk, exc - gE, gE);
            gI = fmaf(dtk, inh - gI, gI);
            gN = fmaf(dtk, nm  - gN, gN);

            // rotate near window down by one slot; lane 31 becomes fresh slot t+32
            float rB = __shfl_down_sync(0xffffffffu, PB, 1);
            float rF = __shfl_down_sync(0xffffffffu, PF, 1);
            float rL = __shfl_down_sync(0xffffffffu, PL, 1);
            bool fresh = (lane == 31);
            PB = fmaf(Kn.x, s2, fresh ? 0.f : rB);
            PF = fmaf(Kn.y, s2, fresh ? 0.f : rF);
            PL = fmaf(Kn.z, s2, fresh ? 0.f : rL);

            // far scatter (read >=33 steps later; synced per trial)
            int sb = t + 1 + lane;
            float4 A1 = Acc[sb + 32];
            A1.x = fmaf(K1.x, s2, A1.x); A1.y = fmaf(K1.y, s2, A1.y); A1.z = fmaf(K1.z, s2, A1.z);
            Acc[sb + 32] = A1;
            float4 A2 = Acc[sb + 64];
            A2.x = fmaf(K2.x, s2, A2.x); A2.y = fmaf(K2.y, s2, A2.y); A2.z = fmaf(K2.z, s2, A2.z);
            Acc[sb + 64] = A2;
            float4 A3 = Acc[sb + 96];
            A3.x = fmaf(K3.x, s2, A3.x); A3.y = fmaf(K3.y, s2, A3.y); A3.z = fmaf(K3.z, s2, A3.z);
            Acc[sb + 96] = A3;
            if (tail) {
                int dend = dmax;
                if (dend > ACCN - 2 - t) dend = ACCN - 2 - t;  // never-read slots skipped
                for (int d = 128 + lane; d <= dend; d += 32) {
                    float4 Kv = Ksm[d];
                    float4 Av = Acc[t + 1 + d];
                    Av.x = fmaf(Kv.x, s2, Av.x); Av.y = fmaf(Kv.y, s2, Av.y); Av.z = fmaf(Kv.z, s2, Av.z);
                    Acc[t + 1 + d] = Av;
                }
            }
            t++;
        }
        __syncwarp();
        if (lane == 2) g_Vsnap[tr * NODE + i] = V;   // population 2's V
    }
}

// ---------------------------------------------------------------------------
// EEG: block = output o; coalesced lmd row in smem; 8 warps x 5 trials.
// ---------------------------------------------------------------------------
__global__ void __launch_bounds__(256) eeg_kernel(
    const float* __restrict__ lm, const float* __restrict__ theta,
    float* __restrict__ out)
{
    int o = blockIdx.x;
    int tid = threadIdx.x;
    int w = tid >> 5, lane = tid & 31;
    __shared__ float lmd[NODE];
    for (int i = tid; i < NODE; i += 256) lmd[i] = lm[o * NODE + i] - g_colmean[i];
    __syncthreads();
    float cy0 = theta[22], y0v = theta[19];
    for (int tr = w; tr < TRS; tr += 8) {
        const float* Vs = g_Vsnap + tr * NODE;
        float acc = 0.f;
        for (int i = lane; i < NODE; i += 32) acc = fmaf(lmd[i], Vs[i], acc);
#pragma unroll
        for (int off = 16; off; off >>= 1) acc += __shfl_xor_sync(0xffffffffu, acc, off);
        if (lane == 0) out[tr * OUTN + o] = cy0 * acc - y0v;
    }
}

// ---------------------------------------------------------------------------
extern "C" void kernel_launch(void* const* d_in, const int* in_sizes, int n_in,
                              void* d_out, int out_size)
{
    const float* ext   = (const float*)d_in[0];
    const float* hx    = (const float*)d_in[1];
    const float* hE    = (const float*)d_in[2];
    const float* sc    = (const float*)d_in[3];
    const float* dist  = (const float*)d_in[4];
    const float* wbb   = (const float*)d_in[5];
    const float* wff   = (const float*)d_in[6];
    const float* wll   = (const float*)d_in[7];
    const float* lm    = (const float*)d_in[8];
    const float* theta = (const float*)d_in[9];
    float* out = (float*)d_out;

    prep_kernel<<<NODE, 128>>>(wbb, wff, wll, sc, dist, theta);
    p2_norms<<<1, 512>>>(lm);
    sim_kernel<<<NODE, 128>>>(ext, hx, hE, theta);
    eeg_kernel<<<OUTN, 256>>>(lm, theta, out);
}